// round 1
// baseline (speedup 1.0000x reference)
#include <cuda_runtime.h>
#include <math.h>

// Fused MLP chain: 6 GEMM+activation launches, ping-pong through device scratch.
// fp32 throughput doubled via Blackwell packed fma.rn.f32x2 (FFMA2).

#define BM 128
#define BN 128
#define BK 16
#define PAD 4
#define LDA (BM + PAD)   // 132
#define LDB (BN + PAD)   // 132

typedef unsigned long long ull;

// Scratch for intermediate activations (no cudaMalloc allowed).
__device__ float g_buf0[65536 * 512];
__device__ float g_buf1[65536 * 512];

__device__ __forceinline__ ull pack2(float x, float y) {
    ull r;
    asm("mov.b64 %0, {%1, %2};" : "=l"(r) : "f"(x), "f"(y));
    return r;
}
__device__ __forceinline__ void fma2(ull& d, ull a, ull b) {
    asm("fma.rn.f32x2 %0, %1, %2, %0;" : "+l"(d) : "l"(a), "l"(b));
}
__device__ __forceinline__ float2 unpack2(ull v) {
    float2 f;
    asm("mov.b64 {%0, %1}, %2;" : "=f"(f.x), "=f"(f.y) : "l"(v));
    return f;
}

// Per-column activation select + clip (matches jax reference).
__device__ __forceinline__ float act_clip(float h, int f, float mx) {
    float o;
    if (f == 0) {
        o = fmaxf(h, 0.0f);                       // relu
    } else if (f == 1) {
        o = 1.0f / (1.0f + expf(-h));             // sigmoid
    } else if (f == 2) {
        o = tanhf(h);                             // tanh
    } else if (f == 3) {
        o = (h > 0.0f) ? h : 0.1f * h;            // leaky relu(0.1)
    } else {
        const float lam = 1.0507009873554805f;
        const float alp = 1.6732632423543772f;
        o = (h > 0.0f) ? lam * h : lam * alp * (expf(h) - 1.0f);  // selu
    }
    return fminf(o, mx);
}

// C[M, N] = act(A[M, 512] @ W[N, 512]^T + bias), per-column act/clip.
// M multiple of 128, N multiple of 128, K = 512 fixed.
__global__ __launch_bounds__(256, 2)
void gemm_act_kernel(const float* __restrict__ A, const float* __restrict__ W,
                     const float* __restrict__ bias, const int* __restrict__ fid,
                     const float* __restrict__ mcap, float* __restrict__ C, int N)
{
    __shared__ __align__(16) float As[BK][LDA];
    __shared__ __align__(16) float Bs[BK][LDB];
    const int K = 512;

    const int tid   = threadIdx.x;
    const int mBase = blockIdx.y * BM;
    const int nBase = blockIdx.x * BN;
    const int row0  = (tid >> 4) * 8;   // 16 row-groups
    const int col0  = (tid & 15) * 8;   // 16 col-groups

    ull acc[8][4];
#pragma unroll
    for (int i = 0; i < 8; i++)
#pragma unroll
        for (int j = 0; j < 4; j++) acc[i][j] = 0ull;

    const float* Ab = A + (size_t)mBase * K;
    const float* Wb = W + (size_t)nBase * K;

    for (int k0 = 0; k0 < K; k0 += BK) {
        // Load 128x16 tiles of A and W (transposed into [k][m]/[k][n]).
        // 512 float4 per tile; 256 threads x 2.
#pragma unroll
        for (int l = 0; l < 2; l++) {
            int idx = tid + l * 256;
            int r   = idx >> 2;          // 0..127
            int c4  = (idx & 3) * 4;     // 0,4,8,12
            float4 av = *(const float4*)(Ab + (size_t)r * K + k0 + c4);
            As[c4 + 0][r] = av.x; As[c4 + 1][r] = av.y;
            As[c4 + 2][r] = av.z; As[c4 + 3][r] = av.w;
            float4 wv = *(const float4*)(Wb + (size_t)r * K + k0 + c4);
            Bs[c4 + 0][r] = wv.x; Bs[c4 + 1][r] = wv.y;
            Bs[c4 + 2][r] = wv.z; Bs[c4 + 3][r] = wv.w;
        }
        __syncthreads();

#pragma unroll
        for (int k = 0; k < BK; k++) {
            float4 a0 = *(const float4*)&As[k][row0];
            float4 a1 = *(const float4*)&As[k][row0 + 4];
            ull b2[4];
            const ull* bp = (const ull*)&Bs[k][col0];
            b2[0] = bp[0]; b2[1] = bp[1]; b2[2] = bp[2]; b2[3] = bp[3];
            float av[8] = {a0.x, a0.y, a0.z, a0.w, a1.x, a1.y, a1.z, a1.w};
#pragma unroll
            for (int i = 0; i < 8; i++) {
                ull a2 = pack2(av[i], av[i]);
#pragma unroll
                for (int j = 0; j < 4; j++) fma2(acc[i][j], a2, b2[j]);
            }
        }
        __syncthreads();
    }

    // Epilogue: bias + per-column activation + clip, vectorized store.
    float bv[8]; int fv[8]; float mv[8];
#pragma unroll
    for (int j = 0; j < 8; j++) {
        int c = nBase + col0 + j;
        bv[j] = bias[c];
        fv[j] = fid[c];
        mv[j] = mcap[c];
    }
#pragma unroll
    for (int i = 0; i < 8; i++) {
        int r = mBase + row0 + i;
        float res[8];
#pragma unroll
        for (int j = 0; j < 4; j++) {
            float2 v = unpack2(acc[i][j]);
            res[2 * j]     = act_clip(v.x + bv[2 * j],     fv[2 * j],     mv[2 * j]);
            res[2 * j + 1] = act_clip(v.y + bv[2 * j + 1], fv[2 * j + 1], mv[2 * j + 1]);
        }
        float* cp = C + (size_t)r * N + nBase + col0;
        *(float4*)(cp)     = make_float4(res[0], res[1], res[2], res[3]);
        *(float4*)(cp + 4) = make_float4(res[4], res[5], res[6], res[7]);
    }
}

extern "C" void kernel_launch(void* const* d_in, const int* in_sizes, int n_in,
                              void* d_out, int out_size)
{
    const float* input  = (const float*)d_in[0];   // [65536, 512]
    const float* W_in   = (const float*)d_in[1];   // [512, 512]
    const float* b_in   = (const float*)d_in[2];   // [512]
    const float* W_h    = (const float*)d_in[3];   // [4, 512, 512]
    const float* b_h    = (const float*)d_in[4];   // [4, 512]
    const float* W_out  = (const float*)d_in[5];   // [128, 512]
    const float* b_out  = (const float*)d_in[6];   // [128]
    const float* m_in   = (const float*)d_in[7];   // [512]
    const float* m_h    = (const float*)d_in[8];   // [4, 512]
    const float* m_out  = (const float*)d_in[9];   // [128]
    const int*   fid_in  = (const int*)d_in[10];   // [512]
    const int*   fid_h   = (const int*)d_in[11];   // [4, 512]
    const int*   fid_out = (const int*)d_in[12];   // [128]
    float* out = (float*)d_out;                    // [65536, 128]

    float *buf0, *buf1;
    cudaGetSymbolAddress((void**)&buf0, g_buf0);
    cudaGetSymbolAddress((void**)&buf1, g_buf1);

    const int B = 65536, X = 512, DOUT = 128;
    dim3 blk(256);
    dim3 grid512(X / BN, B / BM);     // (4, 512)
    dim3 grid128(DOUT / BN, B / BM);  // (1, 512)

    // Input layer
    gemm_act_kernel<<<grid512, blk>>>(input, W_in, b_in, fid_in, m_in, buf0, X);

    // Hidden layers (Z = 4), ping-pong buffers
    const float* cur = buf0;
    float* nxt = buf1;
    for (int i = 0; i < 4; i++) {
        gemm_act_kernel<<<grid512, blk>>>(cur, W_h + (size_t)i * X * X,
                                          b_h + i * X, fid_h + i * X, m_h + i * X,
                                          nxt, X);
        float* t = (float*)cur; cur = nxt; nxt = t;
    }

    // Output layer
    gemm_act_kernel<<<grid128, blk>>>(cur, W_out, b_out, fid_out, m_out, out, DOUT);
}

// round 3
// speedup vs baseline: 1.4524x; 1.4524x over previous
#include <cuda_runtime.h>
#include <cuda_bf16.h>
#include <math.h>
#include <stdint.h>

// ============================================================
// mma.sync (HMMA) bf16-split GEMM chain for the 6-layer MLP.
// fp32 x fp32 emulated as (hi+lo bf16): hh + hl + lh, fp32 accum.
// No tcgen05 (harness compiles via compute_103 which rejects it).
// ============================================================

#define BATCH 65536
#define XDIM 512

// ---------- scratch (no cudaMalloc allowed) ----------
__device__ __nv_bfloat16 g_ah0[(size_t)BATCH * XDIM];
__device__ __nv_bfloat16 g_al0[(size_t)BATCH * XDIM];
__device__ __nv_bfloat16 g_ah1[(size_t)BATCH * XDIM];
__device__ __nv_bfloat16 g_al1[(size_t)BATCH * XDIM];
#define W_TOTAL (5 * 512 * 512 + 128 * 512)
__device__ __nv_bfloat16 g_wh[W_TOTAL];
__device__ __nv_bfloat16 g_wl[W_TOTAL];

// ---------- PTX helpers ----------
__device__ __forceinline__ uint32_t smem_u32(const void* p) {
    uint32_t a;
    asm("{ .reg .u64 t; cvta.to.shared.u64 t, %1; cvt.u32.u64 %0, t; }" : "=r"(a) : "l"(p));
    return a;
}
#define CP_ASYNC16(dst, src) \
    asm volatile("cp.async.cg.shared.global [%0], [%1], 16;" :: "r"(dst), "l"(src))
#define CP_COMMIT() asm volatile("cp.async.commit_group;" ::: "memory")
#define CP_WAIT(n)  asm volatile("cp.async.wait_group %0;" :: "n"(n) : "memory")

__device__ __forceinline__ void ldsm4(uint32_t r[4], uint32_t addr) {
    asm volatile("ldmatrix.sync.aligned.m8n8.x4.shared.b16 {%0,%1,%2,%3}, [%4];"
                 : "=r"(r[0]), "=r"(r[1]), "=r"(r[2]), "=r"(r[3]) : "r"(addr));
}
__device__ __forceinline__ void mma16816(float c[4], const uint32_t a[4], const uint32_t b[2]) {
    asm volatile(
        "mma.sync.aligned.m16n8k16.row.col.f32.bf16.bf16.f32 "
        "{%0,%1,%2,%3}, {%4,%5,%6,%7}, {%8,%9}, {%0,%1,%2,%3};"
        : "+f"(c[0]), "+f"(c[1]), "+f"(c[2]), "+f"(c[3])
        : "r"(a[0]), "r"(a[1]), "r"(a[2]), "r"(a[3]), "r"(b[0]), "r"(b[1]));
}

// ---------- activation ----------
__device__ __forceinline__ float act_clip(float h, int f, float mx) {
    float o;
    if (f == 0) {
        o = fmaxf(h, 0.0f);
    } else if (f == 1) {
        o = 1.0f / (1.0f + expf(-h));
    } else if (f == 2) {
        o = tanhf(h);
    } else if (f == 3) {
        o = (h > 0.0f) ? h : 0.1f * h;
    } else {
        const float lam = 1.0507009873554805f;
        const float alp = 1.6732632423543772f;
        o = (h > 0.0f) ? lam * h : lam * alp * expm1f(h);
    }
    return fminf(o, mx);
}

__device__ __forceinline__ uint32_t pack_bf2(float x0, float x1) {
    __nv_bfloat16 b0 = __float2bfloat16(x0);
    __nv_bfloat16 b1 = __float2bfloat16(x1);
    return (uint32_t)__bfloat16_as_ushort(b0) | ((uint32_t)__bfloat16_as_ushort(b1) << 16);
}

// ---------- split fp32 -> hi/lo bf16 ----------
__global__ __launch_bounds__(256)
void split_kernel(const float* __restrict__ src, __nv_bfloat16* __restrict__ hi,
                  __nv_bfloat16* __restrict__ lo, int n)
{
    int i = (blockIdx.x * 256 + threadIdx.x) * 4;
    if (i >= n) return;
    float4 v = *(const float4*)(src + i);
    float x[4] = {v.x, v.y, v.z, v.w};
    float h[4], r[4];
#pragma unroll
    for (int k = 0; k < 4; k++) {
        h[k] = __bfloat162float(__float2bfloat16(x[k]));
        r[k] = x[k] - h[k];
    }
    *(uint2*)(hi + i) = make_uint2(pack_bf2(h[0], h[1]), pack_bf2(h[2], h[3]));
    *(uint2*)(lo + i) = make_uint2(pack_bf2(r[0], r[1]), pack_bf2(r[2], r[3]));
}

// ============================================================
// C[128,128] tile of act(A @ W^T + b). K = 512.
// A planes [B,512] bf16 hi/lo; W planes [N_total,512] bf16 hi/lo.
// 8 warps: 2 (M) x 4 (N); warp tile 64x32; mma.m16n8k16.
// K-chunks of 32; double-buffered smem via cp.async.
// ============================================================
template<bool OUT_FP32>
__global__ __launch_bounds__(256, 1)
void bnn_gemm_kernel(const __nv_bfloat16* __restrict__ Ahi,
                     const __nv_bfloat16* __restrict__ Alo,
                     const __nv_bfloat16* __restrict__ Whi,
                     const __nv_bfloat16* __restrict__ Wlo,
                     const float* __restrict__ bias,
                     const int* __restrict__ fid,
                     const float* __restrict__ mcap,
                     float* __restrict__ OutF,
                     __nv_bfloat16* __restrict__ Ohi,
                     __nv_bfloat16* __restrict__ Olo,
                     int N_total)
{
    extern __shared__ char smem[];
    constexpr int K = 512;
    constexpr int PLANE = 128 * 64;     // 128 rows x 32 bf16 (64 B)
    constexpr int STAGE = 4 * PLANE;    // Ah, Al, Bh, Bl = 32 KB

    const int tid  = threadIdx.x;
    const int lane = tid & 31;
    const int wid  = tid >> 5;
    const int mBase = blockIdx.y * 128;
    const int nBase = blockIdx.x * 128;
    const uint32_t sb = smem_u32(smem);

    const int mw = (wid & 1) * 64;      // warp offset in M
    const int nw = (wid >> 1) * 32;     // warp offset in N

    // ldmatrix lane roles
    const int lA_r = (lane & 7) + ((lane >> 3) & 1) * 8;   // m-row within 16-tile
    const int lA_c = (lane >> 4) & 1;                      // k 16B-chunk bit
    const int lB_r = (lane & 7) + ((lane >> 4) & 1) * 8;   // n-row
    const int lB_c = (lane >> 3) & 1;

    float acc[4][4][4];
#pragma unroll
    for (int i = 0; i < 4; i++)
#pragma unroll
        for (int j = 0; j < 4; j++)
#pragma unroll
            for (int v = 0; v < 4; v++) acc[i][j][v] = 0.0f;

    // ---- async stage loader: chunk c -> stage s ----
    auto prefetch = [&](int c, int s) {
        const int k0 = c * 32;
        const uint32_t dstb = sb + s * STAGE;
        const int q = tid & 3;                       // 16B chunk in row
#pragma unroll
        for (int i = 0; i < 8; i++) {
            const int p = i >> 1;                    // plane 0..3
            const int r = (tid + (i & 1) * 256) >> 2;  // row 0..127
            uint32_t dst = dstb + p * PLANE + r * 64 + ((q * 16) ^ ((r & 6) << 3));
            const __nv_bfloat16* src;
            if (p == 0)      src = Ahi + (size_t)(mBase + r) * K + k0 + q * 8;
            else if (p == 1) src = Alo + (size_t)(mBase + r) * K + k0 + q * 8;
            else if (p == 2) src = Whi + (size_t)(nBase + r) * K + k0 + q * 8;
            else             src = Wlo + (size_t)(nBase + r) * K + k0 + q * 8;
            CP_ASYNC16(dst, src);
        }
        CP_COMMIT();
    };

    prefetch(0, 0);

#pragma unroll 1
    for (int c = 0; c < 16; c++) {
        if (c + 1 < 16) {
            prefetch(c + 1, (c + 1) & 1);
            CP_WAIT(1);
        } else {
            CP_WAIT(0);
        }
        __syncthreads();

        const uint32_t aH = sb + (c & 1) * STAGE;
        const uint32_t aL = aH + PLANE;
        const uint32_t bH = aH + 2 * PLANE;
        const uint32_t bL = aH + 3 * PLANE;

#pragma unroll
        for (int ks = 0; ks < 2; ks++) {
            uint32_t ah[4][4], al[4][4], bh[4][2], bl[4][2];
            const int cA = ks * 2 + lA_c;
            const int cB = ks * 2 + lB_c;
#pragma unroll
            for (int mi = 0; mi < 4; mi++) {
                const int r = mw + mi * 16 + lA_r;
                const uint32_t off = r * 64 + ((cA * 16) ^ ((r & 6) << 3));
                ldsm4(ah[mi], aH + off);
                ldsm4(al[mi], aL + off);
            }
#pragma unroll
            for (int t = 0; t < 2; t++) {
                const int r = nw + t * 16 + lB_r;
                const uint32_t off = r * 64 + ((cB * 16) ^ ((r & 6) << 3));
                uint32_t tmp[4];
                ldsm4(tmp, bH + off);
                bh[2 * t][0] = tmp[0]; bh[2 * t][1] = tmp[1];
                bh[2 * t + 1][0] = tmp[2]; bh[2 * t + 1][1] = tmp[3];
                ldsm4(tmp, bL + off);
                bl[2 * t][0] = tmp[0]; bl[2 * t][1] = tmp[1];
                bl[2 * t + 1][0] = tmp[2]; bl[2 * t + 1][1] = tmp[3];
            }
#pragma unroll
            for (int mi = 0; mi < 4; mi++)
#pragma unroll
                for (int ni = 0; ni < 4; ni++) {
                    mma16816(acc[mi][ni], ah[mi], bh[ni]);   // hh
                    mma16816(acc[mi][ni], ah[mi], bl[ni]);   // hl
                    mma16816(acc[mi][ni], al[mi], bh[ni]);   // lh
                }
        }
        __syncthreads();
    }

    // ---------- epilogue ----------
    const int colq = (lane & 3) * 2;
#pragma unroll
    for (int ni = 0; ni < 4; ni++) {
        const int col = nBase + nw + ni * 8 + colq;
        const float2 b2 = *(const float2*)(bias + col);
        const int2   f2 = *(const int2*)(fid + col);
        const float2 m2 = *(const float2*)(mcap + col);
#pragma unroll
        for (int mi = 0; mi < 4; mi++) {
#pragma unroll
            for (int h = 0; h < 2; h++) {
                const int row = mBase + mw + mi * 16 + (lane >> 2) + h * 8;
                const float r0 = act_clip(acc[mi][ni][h * 2 + 0] + b2.x, f2.x, m2.x);
                const float r1 = act_clip(acc[mi][ni][h * 2 + 1] + b2.y, f2.y, m2.y);
                const size_t o = (size_t)row * N_total + col;
                if (OUT_FP32) {
                    *(float2*)(OutF + o) = make_float2(r0, r1);
                } else {
                    const float h0 = __bfloat162float(__float2bfloat16(r0));
                    const float h1 = __bfloat162float(__float2bfloat16(r1));
                    *(uint32_t*)(Ohi + o) = pack_bf2(r0, r1);
                    *(uint32_t*)(Olo + o) = pack_bf2(r0 - h0, r1 - h1);
                }
            }
        }
    }
}

// ============================================================
extern "C" void kernel_launch(void* const* d_in, const int* in_sizes, int n_in,
                              void* d_out, int out_size)
{
    const float* input  = (const float*)d_in[0];
    const float* W_in   = (const float*)d_in[1];
    const float* b_in   = (const float*)d_in[2];
    const float* W_h    = (const float*)d_in[3];
    const float* b_h    = (const float*)d_in[4];
    const float* W_out  = (const float*)d_in[5];
    const float* b_out  = (const float*)d_in[6];
    const float* m_in   = (const float*)d_in[7];
    const float* m_h    = (const float*)d_in[8];
    const float* m_out  = (const float*)d_in[9];
    const int*   fid_in  = (const int*)d_in[10];
    const int*   fid_h   = (const int*)d_in[11];
    const int*   fid_out = (const int*)d_in[12];
    float* out = (float*)d_out;

    __nv_bfloat16 *ah0, *al0, *ah1, *al1, *wh, *wl;
    cudaGetSymbolAddress((void**)&ah0, g_ah0);
    cudaGetSymbolAddress((void**)&al0, g_al0);
    cudaGetSymbolAddress((void**)&ah1, g_ah1);
    cudaGetSymbolAddress((void**)&al1, g_al1);
    cudaGetSymbolAddress((void**)&wh, g_wh);
    cudaGetSymbolAddress((void**)&wl, g_wl);

    constexpr int SMEM = 2 * 4 * 128 * 64;   // 65536
    cudaFuncSetAttribute(bnn_gemm_kernel<false>,
                         cudaFuncAttributeMaxDynamicSharedMemorySize, SMEM);
    cudaFuncSetAttribute(bnn_gemm_kernel<true>,
                         cudaFuncAttributeMaxDynamicSharedMemorySize, SMEM);

    const int B = BATCH, X = XDIM, DOUT = 128;
    const int WIN_OFF = 0, WH_OFF = X * X, WOUT_OFF = 5 * X * X;

    // fp32 -> hi/lo bf16 splits
    split_kernel<<<(B * X) / 1024, 256>>>(input, ah0, al0, B * X);
    split_kernel<<<(X * X) / 1024, 256>>>(W_in, wh + WIN_OFF, wl + WIN_OFF, X * X);
    split_kernel<<<(4 * X * X) / 1024, 256>>>(W_h, wh + WH_OFF, wl + WH_OFF, 4 * X * X);
    split_kernel<<<(DOUT * X) / 1024, 256>>>(W_out, wh + WOUT_OFF, wl + WOUT_OFF, DOUT * X);

    dim3 blk(256);
    dim3 grid512(X / 128, B / 128);    // (4, 512)
    dim3 grid128(1, B / 128);          // (1, 512)

    // layer 1
    bnn_gemm_kernel<false><<<grid512, blk, SMEM>>>(
        ah0, al0, wh + WIN_OFF, wl + WIN_OFF, b_in, fid_in, m_in,
        nullptr, ah1, al1, X);

    // hidden layers
    __nv_bfloat16 *ch = ah1, *cl = al1, *nh = ah0, *nl = al0;
    for (int i = 0; i < 4; i++) {
        bnn_gemm_kernel<false><<<grid512, blk, SMEM>>>(
            ch, cl, wh + WH_OFF + i * X * X, wl + WH_OFF + i * X * X,
            b_h + i * X, fid_h + i * X, m_h + i * X,
            nullptr, nh, nl, X);
        __nv_bfloat16* t;
        t = ch; ch = nh; nh = t;
        t = cl; cl = nl; nl = t;
    }

    // output layer -> fp32
    bnn_gemm_kernel<true><<<grid128, blk, SMEM>>>(
        ch, cl, wh + WOUT_OFF, wl + WOUT_OFF, b_out, fid_out, m_out,
        out, nullptr, nullptr, DOUT);
}

// round 4
// speedup vs baseline: 1.5189x; 1.0458x over previous
#include <cuda_runtime.h>
#include <cuda_fp16.h>
#include <math.h>
#include <stdint.h>

// ============================================================
// mma.sync (HMMA) fp16-split GEMM chain for the 6-layer MLP.
// fp32 x fp32 emulated as (hi+lo fp16): hh + hl + lh, fp32 accum.
// fp16 split: repr error ~2^-24 per operand (vs 2^-17 for bf16).
// ============================================================

#define BATCH 65536
#define XDIM 512

// ---------- scratch (no cudaMalloc allowed) ----------
__device__ __half g_ah0[(size_t)BATCH * XDIM];
__device__ __half g_al0[(size_t)BATCH * XDIM];
__device__ __half g_ah1[(size_t)BATCH * XDIM];
__device__ __half g_al1[(size_t)BATCH * XDIM];
#define W_TOTAL (5 * 512 * 512 + 128 * 512)
__device__ __half g_wh[W_TOTAL];
__device__ __half g_wl[W_TOTAL];

// ---------- PTX helpers ----------
__device__ __forceinline__ uint32_t smem_u32(const void* p) {
    uint32_t a;
    asm("{ .reg .u64 t; cvta.to.shared.u64 t, %1; cvt.u32.u64 %0, t; }" : "=r"(a) : "l"(p));
    return a;
}
#define CP_ASYNC16(dst, src) \
    asm volatile("cp.async.cg.shared.global [%0], [%1], 16;" :: "r"(dst), "l"(src))
#define CP_COMMIT() asm volatile("cp.async.commit_group;" ::: "memory")
#define CP_WAIT(n)  asm volatile("cp.async.wait_group %0;" :: "n"(n) : "memory")

__device__ __forceinline__ void ldsm4(uint32_t r[4], uint32_t addr) {
    asm volatile("ldmatrix.sync.aligned.m8n8.x4.shared.b16 {%0,%1,%2,%3}, [%4];"
                 : "=r"(r[0]), "=r"(r[1]), "=r"(r[2]), "=r"(r[3]) : "r"(addr));
}
__device__ __forceinline__ void mma16816(float c[4], const uint32_t a[4], const uint32_t* b) {
    asm volatile(
        "mma.sync.aligned.m16n8k16.row.col.f32.f16.f16.f32 "
        "{%0,%1,%2,%3}, {%4,%5,%6,%7}, {%8,%9}, {%0,%1,%2,%3};"
        : "+f"(c[0]), "+f"(c[1]), "+f"(c[2]), "+f"(c[3])
        : "r"(a[0]), "r"(a[1]), "r"(a[2]), "r"(a[3]), "r"(b[0]), "r"(b[1]));
}

// ---------- activation ----------
__device__ __forceinline__ float act_clip(float h, int f, float mx) {
    float o;
    if (f == 0) {
        o = fmaxf(h, 0.0f);
    } else if (f == 1) {
        o = 1.0f / (1.0f + expf(-h));
    } else if (f == 2) {
        o = tanhf(h);
    } else if (f == 3) {
        o = (h > 0.0f) ? h : 0.1f * h;
    } else {
        const float lam = 1.0507009873554805f;
        const float alp = 1.6732632423543772f;
        o = (h > 0.0f) ? lam * h : lam * alp * expm1f(h);
    }
    return fminf(o, mx);
}

__device__ __forceinline__ uint32_t pack_h2(float x0, float x1) {
    __half2 h = __floats2half2_rn(x0, x1);
    return *(uint32_t*)&h;
}

// ---------- split fp32 -> hi/lo fp16 ----------
__global__ __launch_bounds__(256)
void split_kernel(const float* __restrict__ src, __half* __restrict__ hi,
                  __half* __restrict__ lo, int n)
{
    int i = (blockIdx.x * 256 + threadIdx.x) * 4;
    if (i >= n) return;
    float4 v = *(const float4*)(src + i);
    float x[4] = {v.x, v.y, v.z, v.w};
    float h[4], r[4];
#pragma unroll
    for (int k = 0; k < 4; k++) {
        h[k] = __half2float(__float2half_rn(x[k]));
        r[k] = x[k] - h[k];
    }
    *(uint2*)(hi + i) = make_uint2(pack_h2(h[0], h[1]), pack_h2(h[2], h[3]));
    *(uint2*)(lo + i) = make_uint2(pack_h2(r[0], r[1]), pack_h2(r[2], r[3]));
}

// ============================================================
// C[128, N_TILE] tile of act(A @ W^T + b). K = 512.
// 8 warps: 2(M) x 4(N); warp tile 64 x (N_TILE/4).
// K-chunks of 32, double-buffered cp.async.
// ============================================================
template<int N_TILE, bool OUT_FP32>
__global__ __launch_bounds__(256, 1)
void bnn_gemm_kernel(const __half* __restrict__ Ahi,
                     const __half* __restrict__ Alo,
                     const __half* __restrict__ Whi,
                     const __half* __restrict__ Wlo,
                     const float* __restrict__ bias,
                     const int* __restrict__ fid,
                     const float* __restrict__ mcap,
                     float* __restrict__ OutF,
                     __half* __restrict__ Ohi,
                     __half* __restrict__ Olo,
                     int N_total)
{
    extern __shared__ char smem[];
    constexpr int K  = 512;
    constexpr int WN = N_TILE / 4;       // 64 or 32 cols per warp
    constexpr int TT = WN / 16;          // t-tiles (16 cols each): 4 or 2
    constexpr int NI = WN / 8;           // n8 sub-tiles: 8 or 4

    // smem stage layout: rows of 64B. [Ah 128 | Al 128 | Bh N_TILE | Bl N_TILE]
    constexpr int ROWS_TOT = 256 + 2 * N_TILE;
    constexpr int STAGE    = ROWS_TOT * 64;
    constexpr int AH_OFF = 0;
    constexpr int AL_OFF = 128 * 64;
    constexpr int BH_OFF = 256 * 64;
    constexpr int BL_OFF = (256 + N_TILE) * 64;

    const int tid  = threadIdx.x;
    const int lane = tid & 31;
    const int wid  = tid >> 5;
    const int mBase = blockIdx.y * 128;
    const int nBase = blockIdx.x * N_TILE;
    const uint32_t sb = smem_u32(smem);

    const int mw = (wid & 1) * 64;       // warp M offset
    const int nw = (wid >> 1) * WN;      // warp N offset

    // ldmatrix lane roles
    const int lA_r = (lane & 7) + ((lane >> 3) & 1) * 8;
    const int lA_c = (lane >> 4) & 1;
    const int lB_r = (lane & 7) + ((lane >> 4) & 1) * 8;
    const int lB_c = (lane >> 3) & 1;

    float acc[4][NI][4];
#pragma unroll
    for (int i = 0; i < 4; i++)
#pragma unroll
        for (int j = 0; j < NI; j++)
#pragma unroll
            for (int v = 0; v < 4; v++) acc[i][j][v] = 0.0f;

    // ---- async stage loader: chunk c (k cols [32c, 32c+32)) -> stage s ----
    auto prefetch = [&](int c, int s) {
        const int k0 = c * 32;
        const uint32_t dstb = sb + s * STAGE;
        constexpr int ITERS = (ROWS_TOT * 4) / 256;
#pragma unroll
        for (int j = 0; j < ITERS; j++) {
            const int i  = tid + j * 256;
            const int q  = i & 3;
            const int rg = i >> 2;
            const uint32_t dst = dstb + rg * 64 + ((q * 16) ^ ((rg & 6) << 3));
            const __half* src;
            if (rg < 128)                 src = Ahi + (size_t)(mBase + rg) * K + k0 + q * 8;
            else if (rg < 256)            src = Alo + (size_t)(mBase + rg - 128) * K + k0 + q * 8;
            else if (rg < 256 + N_TILE)   src = Whi + (size_t)(nBase + rg - 256) * K + k0 + q * 8;
            else                          src = Wlo + (size_t)(nBase + rg - 256 - N_TILE) * K + k0 + q * 8;
            CP_ASYNC16(dst, src);
        }
        CP_COMMIT();
    };

    prefetch(0, 0);

#pragma unroll 1
    for (int c = 0; c < 16; c++) {
        if (c + 1 < 16) {
            prefetch(c + 1, (c + 1) & 1);
            CP_WAIT(1);
        } else {
            CP_WAIT(0);
        }
        __syncthreads();

        const uint32_t stg = sb + (c & 1) * STAGE;
        const uint32_t aH = stg + AH_OFF;
        const uint32_t aL = stg + AL_OFF;
        const uint32_t bH = stg + BH_OFF;
        const uint32_t bL = stg + BL_OFF;

#pragma unroll
        for (int ks = 0; ks < 2; ks++) {
            // A fragments: 64 rows x k16, hi + lo planes
            uint32_t ah[4][4], al[4][4];
            const int cA = ks * 2 + lA_c;
#pragma unroll
            for (int mi = 0; mi < 4; mi++) {
                const int r = mw + mi * 16 + lA_r;
                const uint32_t off = r * 64 + ((cA * 16) ^ ((r & 6) << 3));
                ldsm4(ah[mi], aH + off);
                ldsm4(al[mi], aL + off);
            }
            const int cB = ks * 2 + lB_c;
            // per 16-col t-tile: load B frags (hi+lo), then 4x2x3 MMAs
#pragma unroll
            for (int t = 0; t < TT; t++) {
                const int r = nw + t * 16 + lB_r;
                const uint32_t off = r * 64 + ((cB * 16) ^ ((r & 6) << 3));
                uint32_t bh[4], bl[4];
                ldsm4(bh, bH + off);
                ldsm4(bl, bL + off);
#pragma unroll
                for (int mi = 0; mi < 4; mi++) {
                    mma16816(acc[mi][2 * t],     ah[mi], bh);      // hh (n8 #0)
                    mma16816(acc[mi][2 * t],     ah[mi], bl);      // hl
                    mma16816(acc[mi][2 * t],     al[mi], bh);      // lh
                    mma16816(acc[mi][2 * t + 1], ah[mi], bh + 2);  // hh (n8 #1)
                    mma16816(acc[mi][2 * t + 1], ah[mi], bl + 2);  // hl
                    mma16816(acc[mi][2 * t + 1], al[mi], bh + 2);  // lh
                }
            }
        }
        __syncthreads();
    }

    // ---------- epilogue ----------
    const int colq = (lane & 3) * 2;
#pragma unroll
    for (int ni = 0; ni < NI; ni++) {
        const int col = nBase + nw + ni * 8 + colq;
        const float2 b2 = *(const float2*)(bias + col);
        const int2   f2 = *(const int2*)(fid + col);
        const float2 m2 = *(const float2*)(mcap + col);
#pragma unroll
        for (int mi = 0; mi < 4; mi++) {
#pragma unroll
            for (int h = 0; h < 2; h++) {
                const int row = mBase + mw + mi * 16 + (lane >> 2) + h * 8;
                const float r0 = act_clip(acc[mi][ni][h * 2 + 0] + b2.x, f2.x, m2.x);
                const float r1 = act_clip(acc[mi][ni][h * 2 + 1] + b2.y, f2.y, m2.y);
                const size_t o = (size_t)row * N_total + col;
                if (OUT_FP32) {
                    *(float2*)(OutF + o) = make_float2(r0, r1);
                } else {
                    const float h0 = __half2float(__float2half_rn(r0));
                    const float h1 = __half2float(__float2half_rn(r1));
                    *(uint32_t*)(Ohi + o) = pack_h2(r0, r1);
                    *(uint32_t*)(Olo + o) = pack_h2(r0 - h0, r1 - h1);
                }
            }
        }
    }
}

// ============================================================
extern "C" void kernel_launch(void* const* d_in, const int* in_sizes, int n_in,
                              void* d_out, int out_size)
{
    const float* input  = (const float*)d_in[0];
    const float* W_in   = (const float*)d_in[1];
    const float* b_in   = (const float*)d_in[2];
    const float* W_h    = (const float*)d_in[3];
    const float* b_h    = (const float*)d_in[4];
    const float* W_out  = (const float*)d_in[5];
    const float* b_out  = (const float*)d_in[6];
    const float* m_in   = (const float*)d_in[7];
    const float* m_h    = (const float*)d_in[8];
    const float* m_out  = (const float*)d_in[9];
    const int*   fid_in  = (const int*)d_in[10];
    const int*   fid_h   = (const int*)d_in[11];
    const int*   fid_out = (const int*)d_in[12];
    float* out = (float*)d_out;

    __half *ah0, *al0, *ah1, *al1, *wh, *wl;
    cudaGetSymbolAddress((void**)&ah0, g_ah0);
    cudaGetSymbolAddress((void**)&al0, g_al0);
    cudaGetSymbolAddress((void**)&ah1, g_ah1);
    cudaGetSymbolAddress((void**)&al1, g_al1);
    cudaGetSymbolAddress((void**)&wh, g_wh);
    cudaGetSymbolAddress((void**)&wl, g_wl);

    constexpr int SMEM_256 = 2 * (256 + 2 * 256) * 64;   // 98304
    constexpr int SMEM_128 = 2 * (256 + 2 * 128) * 64;   // 65536
    cudaFuncSetAttribute(bnn_gemm_kernel<256, false>,
                         cudaFuncAttributeMaxDynamicSharedMemorySize, SMEM_256);
    cudaFuncSetAttribute(bnn_gemm_kernel<128, true>,
                         cudaFuncAttributeMaxDynamicSharedMemorySize, SMEM_128);

    const int B = BATCH, X = XDIM, DOUT = 128;
    const int WIN_OFF = 0, WH_OFF = X * X, WOUT_OFF = 5 * X * X;

    // fp32 -> hi/lo fp16 splits
    split_kernel<<<(B * X) / 1024, 256>>>(input, ah0, al0, B * X);
    split_kernel<<<(X * X) / 1024, 256>>>(W_in, wh + WIN_OFF, wl + WIN_OFF, X * X);
    split_kernel<<<(4 * X * X) / 1024, 256>>>(W_h, wh + WH_OFF, wl + WH_OFF, 4 * X * X);
    split_kernel<<<(DOUT * X) / 1024, 256>>>(W_out, wh + WOUT_OFF, wl + WOUT_OFF, DOUT * X);

    dim3 blk(256);
    dim3 grid512(X / 256, B / 128);    // (2, 512)
    dim3 grid128(1, B / 128);          // (1, 512)

    // layer 1
    bnn_gemm_kernel<256, false><<<grid512, blk, SMEM_256>>>(
        ah0, al0, wh + WIN_OFF, wl + WIN_OFF, b_in, fid_in, m_in,
        nullptr, ah1, al1, X);

    // hidden layers
    __half *ch = ah1, *cl = al1, *nh = ah0, *nl = al0;
    for (int i = 0; i < 4; i++) {
        bnn_gemm_kernel<256, false><<<grid512, blk, SMEM_256>>>(
            ch, cl, wh + WH_OFF + i * X * X, wl + WH_OFF + i * X * X,
            b_h + i * X, fid_h + i * X, m_h + i * X,
            nullptr, nh, nl, X);
        __half* t;
        t = ch; ch = nh; nh = t;
        t = cl; cl = nl; nl = t;
    }

    // output layer -> fp32
    bnn_gemm_kernel<128, true><<<grid128, blk, SMEM_128>>>(
        ch, cl, wh + WOUT_OFF, wl + WOUT_OFF, b_out, fid_out, m_out,
        out, nullptr, nullptr, DOUT);
}

// round 5
// speedup vs baseline: 1.5883x; 1.0457x over previous
#include <cuda_runtime.h>
#include <cuda_fp16.h>
#include <math.h>
#include <stdint.h>

// ============================================================
// mma.sync (HMMA) fp16-split GEMM chain for the 6-layer MLP.
// fp32 x fp32 emulated as (hi+lo fp16): hh + hl + lh, fp32 accum.
// R5: 4-stage cp.async ring, 1 barrier/chunk, ILP-ordered MMAs.
// ============================================================

#define BATCH 65536
#define XDIM 512

// ---------- scratch (no cudaMalloc allowed) ----------
__device__ __half g_ah0[(size_t)BATCH * XDIM];
__device__ __half g_al0[(size_t)BATCH * XDIM];
__device__ __half g_ah1[(size_t)BATCH * XDIM];
__device__ __half g_al1[(size_t)BATCH * XDIM];
#define W_TOTAL (5 * 512 * 512 + 128 * 512)
__device__ __half g_wh[W_TOTAL];
__device__ __half g_wl[W_TOTAL];

// ---------- PTX helpers ----------
__device__ __forceinline__ uint32_t smem_u32(const void* p) {
    uint32_t a;
    asm("{ .reg .u64 t; cvta.to.shared.u64 t, %1; cvt.u32.u64 %0, t; }" : "=r"(a) : "l"(p));
    return a;
}
#define CP_ASYNC16(dst, src) \
    asm volatile("cp.async.cg.shared.global [%0], [%1], 16;" :: "r"(dst), "l"(src))
#define CP_COMMIT() asm volatile("cp.async.commit_group;" ::: "memory")
#define CP_WAIT(n)  asm volatile("cp.async.wait_group %0;" :: "n"(n) : "memory")

__device__ __forceinline__ void ldsm4(uint32_t r[4], uint32_t addr) {
    asm volatile("ldmatrix.sync.aligned.m8n8.x4.shared.b16 {%0,%1,%2,%3}, [%4];"
                 : "=r"(r[0]), "=r"(r[1]), "=r"(r[2]), "=r"(r[3]) : "r"(addr));
}
__device__ __forceinline__ void mma16816(float c[4], const uint32_t a[4], const uint32_t* b) {
    asm volatile(
        "mma.sync.aligned.m16n8k16.row.col.f32.f16.f16.f32 "
        "{%0,%1,%2,%3}, {%4,%5,%6,%7}, {%8,%9}, {%0,%1,%2,%3};"
        : "+f"(c[0]), "+f"(c[1]), "+f"(c[2]), "+f"(c[3])
        : "r"(a[0]), "r"(a[1]), "r"(a[2]), "r"(a[3]), "r"(b[0]), "r"(b[1]));
}

// ---------- activation ----------
__device__ __forceinline__ float act_clip(float h, int f, float mx) {
    float o;
    if (f == 0) {
        o = fmaxf(h, 0.0f);
    } else if (f == 1) {
        o = 1.0f / (1.0f + expf(-h));
    } else if (f == 2) {
        o = tanhf(h);
    } else if (f == 3) {
        o = (h > 0.0f) ? h : 0.1f * h;
    } else {
        const float lam = 1.0507009873554805f;
        const float alp = 1.6732632423543772f;
        o = (h > 0.0f) ? lam * h : lam * alp * expm1f(h);
    }
    return fminf(o, mx);
}

__device__ __forceinline__ uint32_t pack_h2(float x0, float x1) {
    __half2 h = __floats2half2_rn(x0, x1);
    return *(uint32_t*)&h;
}

// ---------- split fp32 -> hi/lo fp16 ----------
__global__ __launch_bounds__(256)
void split_kernel(const float* __restrict__ src, __half* __restrict__ hi,
                  __half* __restrict__ lo, int n)
{
    int i = (blockIdx.x * 256 + threadIdx.x) * 4;
    if (i >= n) return;
    float4 v = *(const float4*)(src + i);
    float x[4] = {v.x, v.y, v.z, v.w};
    float h[4], r[4];
#pragma unroll
    for (int k = 0; k < 4; k++) {
        h[k] = __half2float(__float2half_rn(x[k]));
        r[k] = x[k] - h[k];
    }
    *(uint2*)(hi + i) = make_uint2(pack_h2(h[0], h[1]), pack_h2(h[2], h[3]));
    *(uint2*)(lo + i) = make_uint2(pack_h2(r[0], r[1]), pack_h2(r[2], r[3]));
}

// ============================================================
// C[128, N_TILE] tile of act(A @ W^T + b). K = 512.
// 8 warps: 2(M) x 4(N); warp tile 64 x (N_TILE/4).
// K-chunks of 32; 4-stage cp.async ring, lookahead 2,
// one __syncthreads per chunk.
// ============================================================
template<int N_TILE, bool OUT_FP32>
__global__ __launch_bounds__(256, 1)
void bnn_gemm_kernel(const __half* __restrict__ Ahi,
                     const __half* __restrict__ Alo,
                     const __half* __restrict__ Whi,
                     const __half* __restrict__ Wlo,
                     const float* __restrict__ bias,
                     const int* __restrict__ fid,
                     const float* __restrict__ mcap,
                     float* __restrict__ OutF,
                     __half* __restrict__ Ohi,
                     __half* __restrict__ Olo,
                     int N_total)
{
    extern __shared__ char smem[];
    constexpr int K  = 512;
    constexpr int NCHUNK = K / 32;       // 16
    constexpr int WN = N_TILE / 4;       // 64 or 32 cols per warp
    constexpr int TT = WN / 16;          // t-tiles: 4 or 2
    constexpr int NI = WN / 8;           // n8 sub-tiles: 8 or 4

    // smem stage layout: rows of 64B. [Ah 128 | Al 128 | Bh N_TILE | Bl N_TILE]
    constexpr int ROWS_TOT = 256 + 2 * N_TILE;
    constexpr int STAGE    = ROWS_TOT * 64;
    constexpr int AL_OFF = 128 * 64;
    constexpr int BH_OFF = 256 * 64;
    constexpr int BL_OFF = (256 + N_TILE) * 64;

    const int tid  = threadIdx.x;
    const int lane = tid & 31;
    const int wid  = tid >> 5;
    const int mBase = blockIdx.y * 128;
    const int nBase = blockIdx.x * N_TILE;
    const uint32_t sb = smem_u32(smem);

    const int mw = (wid & 1) * 64;       // warp M offset
    const int nw = (wid >> 1) * WN;      // warp N offset

    // ldmatrix lane roles
    const int lA_r = (lane & 7) + ((lane >> 3) & 1) * 8;
    const int lA_c = (lane >> 4) & 1;
    const int lB_r = (lane & 7) + ((lane >> 4) & 1) * 8;
    const int lB_c = (lane >> 3) & 1;

    float acc[4][NI][4];
#pragma unroll
    for (int i = 0; i < 4; i++)
#pragma unroll
        for (int j = 0; j < NI; j++)
#pragma unroll
            for (int v = 0; v < 4; v++) acc[i][j][v] = 0.0f;

    // ---- async stage loader: chunk c (k cols [32c, 32c+32)) -> stage s ----
    auto prefetch = [&](int c, int s) {
        const int k0 = c * 32;
        const uint32_t dstb = sb + s * STAGE;
        constexpr int ITERS = (ROWS_TOT * 4) / 256;
#pragma unroll
        for (int j = 0; j < ITERS; j++) {
            const int i  = tid + j * 256;
            const int q  = i & 3;
            const int rg = i >> 2;
            const uint32_t dst = dstb + rg * 64 + ((q * 16) ^ ((rg & 6) << 3));
            const __half* src;
            if (rg < 128)                 src = Ahi + (size_t)(mBase + rg) * K + k0 + q * 8;
            else if (rg < 256)            src = Alo + (size_t)(mBase + rg - 128) * K + k0 + q * 8;
            else if (rg < 256 + N_TILE)   src = Whi + (size_t)(nBase + rg - 256) * K + k0 + q * 8;
            else                          src = Wlo + (size_t)(nBase + rg - 256 - N_TILE) * K + k0 + q * 8;
            CP_ASYNC16(dst, src);
        }
        CP_COMMIT();
    };

    // preload chunks 0, 1 into stages 0, 1
    prefetch(0, 0);
    prefetch(1, 1);

#pragma unroll 1
    for (int c = 0; c < NCHUNK; c++) {
        // lookahead-2 prefetch into stage (c+2)%4: never collides with a
        // laggard warp still computing chunk c-1 (stage (c-1)%4 != (c+2)%4).
        if (c + 2 < NCHUNK) {
            prefetch(c + 2, (c + 2) & 3);
            CP_WAIT(2);                 // pending: c+1, c+2 -> chunk c done
        } else if (c + 2 == NCHUNK) {
            CP_WAIT(1);                 // pending: c+1 -> chunk c done
        } else {
            CP_WAIT(0);                 // last chunk
        }
        __syncthreads();                // publish chunk c; retire stage reads

        const uint32_t stg = sb + (c & 3) * STAGE;
        const uint32_t aH = stg;
        const uint32_t aL = stg + AL_OFF;
        const uint32_t bH = stg + BH_OFF;
        const uint32_t bL = stg + BL_OFF;

#pragma unroll
        for (int ks = 0; ks < 2; ks++) {
            // A fragments: 64 rows x k16, hi + lo planes
            uint32_t ah[4][4], al[4][4];
            const int cA = ks * 2 + lA_c;
#pragma unroll
            for (int mi = 0; mi < 4; mi++) {
                const int r = mw + mi * 16 + lA_r;
                const uint32_t off = r * 64 + ((cA * 16) ^ ((r & 6) << 3));
                ldsm4(ah[mi], aH + off);
                ldsm4(al[mi], aL + off);
            }
            const int cB = ks * 2 + lB_c;
#pragma unroll
            for (int t = 0; t < TT; t++) {
                const int r = nw + t * 16 + lB_r;
                const uint32_t off = r * 64 + ((cB * 16) ^ ((r & 6) << 3));
                uint32_t bh[4], bl[4];
                ldsm4(bh, bH + off);
                ldsm4(bl, bL + off);
                // mi-inner ordering: reuse distance 8 between writes to the
                // same accumulator -> independent HMMA issue.
#pragma unroll
                for (int mi = 0; mi < 4; mi++) mma16816(acc[mi][2 * t],     ah[mi], bh);
#pragma unroll
                for (int mi = 0; mi < 4; mi++) mma16816(acc[mi][2 * t + 1], ah[mi], bh + 2);
#pragma unroll
                for (int mi = 0; mi < 4; mi++) mma16816(acc[mi][2 * t],     ah[mi], bl);
#pragma unroll
                for (int mi = 0; mi < 4; mi++) mma16816(acc[mi][2 * t + 1], ah[mi], bl + 2);
#pragma unroll
                for (int mi = 0; mi < 4; mi++) mma16816(acc[mi][2 * t],     al[mi], bh);
#pragma unroll
                for (int mi = 0; mi < 4; mi++) mma16816(acc[mi][2 * t + 1], al[mi], bh + 2);
            }
        }
    }

    // ---------- epilogue ----------
    const int colq = (lane & 3) * 2;
#pragma unroll
    for (int ni = 0; ni < NI; ni++) {
        const int col = nBase + nw + ni * 8 + colq;
        const float2 b2 = *(const float2*)(bias + col);
        const int2   f2 = *(const int2*)(fid + col);
        const float2 m2 = *(const float2*)(mcap + col);
#pragma unroll
        for (int mi = 0; mi < 4; mi++) {
#pragma unroll
            for (int h = 0; h < 2; h++) {
                const int row = mBase + mw + mi * 16 + (lane >> 2) + h * 8;
                const float r0 = act_clip(acc[mi][ni][h * 2 + 0] + b2.x, f2.x, m2.x);
                const float r1 = act_clip(acc[mi][ni][h * 2 + 1] + b2.y, f2.y, m2.y);
                const size_t o = (size_t)row * N_total + col;
                if (OUT_FP32) {
                    *(float2*)(OutF + o) = make_float2(r0, r1);
                } else {
                    const float h0 = __half2float(__float2half_rn(r0));
                    const float h1 = __half2float(__float2half_rn(r1));
                    *(uint32_t*)(Ohi + o) = pack_h2(r0, r1);
                    *(uint32_t*)(Olo + o) = pack_h2(r0 - h0, r1 - h1);
                }
            }
        }
    }
}

// ============================================================
extern "C" void kernel_launch(void* const* d_in, const int* in_sizes, int n_in,
                              void* d_out, int out_size)
{
    const float* input  = (const float*)d_in[0];
    const float* W_in   = (const float*)d_in[1];
    const float* b_in   = (const float*)d_in[2];
    const float* W_h    = (const float*)d_in[3];
    const float* b_h    = (const float*)d_in[4];
    const float* W_out  = (const float*)d_in[5];
    const float* b_out  = (const float*)d_in[6];
    const float* m_in   = (const float*)d_in[7];
    const float* m_h    = (const float*)d_in[8];
    const float* m_out  = (const float*)d_in[9];
    const int*   fid_in  = (const int*)d_in[10];
    const int*   fid_h   = (const int*)d_in[11];
    const int*   fid_out = (const int*)d_in[12];
    float* out = (float*)d_out;

    __half *ah0, *al0, *ah1, *al1, *wh, *wl;
    cudaGetSymbolAddress((void**)&ah0, g_ah0);
    cudaGetSymbolAddress((void**)&al0, g_al0);
    cudaGetSymbolAddress((void**)&ah1, g_ah1);
    cudaGetSymbolAddress((void**)&al1, g_al1);
    cudaGetSymbolAddress((void**)&wh, g_wh);
    cudaGetSymbolAddress((void**)&wl, g_wl);

    constexpr int SMEM_256 = 4 * (256 + 2 * 256) * 64;   // 196608
    constexpr int SMEM_128 = 4 * (256 + 2 * 128) * 64;   // 131072
    cudaFuncSetAttribute(bnn_gemm_kernel<256, false>,
                         cudaFuncAttributeMaxDynamicSharedMemorySize, SMEM_256);
    cudaFuncSetAttribute(bnn_gemm_kernel<128, true>,
                         cudaFuncAttributeMaxDynamicSharedMemorySize, SMEM_128);

    const int B = BATCH, X = XDIM, DOUT = 128;
    const int WIN_OFF = 0, WH_OFF = X * X, WOUT_OFF = 5 * X * X;

    // fp32 -> hi/lo fp16 splits
    split_kernel<<<(B * X) / 1024, 256>>>(input, ah0, al0, B * X);
    split_kernel<<<(X * X) / 1024, 256>>>(W_in, wh + WIN_OFF, wl + WIN_OFF, X * X);
    split_kernel<<<(4 * X * X) / 1024, 256>>>(W_h, wh + WH_OFF, wl + WH_OFF, 4 * X * X);
    split_kernel<<<(DOUT * X) / 1024, 256>>>(W_out, wh + WOUT_OFF, wl + WOUT_OFF, DOUT * X);

    dim3 blk(256);
    dim3 grid512(X / 256, B / 128);    // (2, 512)
    dim3 grid128(1, B / 128);          // (1, 512)

    // layer 1
    bnn_gemm_kernel<256, false><<<grid512, blk, SMEM_256>>>(
        ah0, al0, wh + WIN_OFF, wl + WIN_OFF, b_in, fid_in, m_in,
        nullptr, ah1, al1, X);

    // hidden layers
    __half *ch = ah1, *cl = al1, *nh = ah0, *nl = al0;
    for (int i = 0; i < 4; i++) {
        bnn_gemm_kernel<256, false><<<grid512, blk, SMEM_256>>>(
            ch, cl, wh + WH_OFF + i * X * X, wl + WH_OFF + i * X * X,
            b_h + i * X, fid_h + i * X, m_h + i * X,
            nullptr, nh, nl, X);
        __half* t;
        t = ch; ch = nh; nh = t;
        t = cl; cl = nl; nl = t;
    }

    // output layer -> fp32
    bnn_gemm_kernel<128, true><<<grid128, blk, SMEM_128>>>(
        ch, cl, wh + WOUT_OFF, wl + WOUT_OFF, b_out, fid_out, m_out,
        out, nullptr, nullptr, DOUT);
}

// round 6
// speedup vs baseline: 2.2883x; 1.4407x over previous
#include <cuda_runtime.h>
#include <cuda_fp16.h>
#include <math.h>
#include <stdint.h>

// ============================================================
// mma.sync (HMMA) fp16-split GEMM chain for the 6-layer MLP.
// fp32 x fp32 emulated as (hi+lo fp16): hh + hl + lh, fp32 accum.
// R6: 128x128 tile, 2 CTAs/SM (4 warps/SMSP), 3-stage ring.
// ============================================================

#define BATCH 65536
#define XDIM 512

// ---------- scratch (no cudaMalloc allowed) ----------
__device__ __half g_ah0[(size_t)BATCH * XDIM];
__device__ __half g_al0[(size_t)BATCH * XDIM];
__device__ __half g_ah1[(size_t)BATCH * XDIM];
__device__ __half g_al1[(size_t)BATCH * XDIM];
#define W_TOTAL (5 * 512 * 512 + 128 * 512)
__device__ __half g_wh[W_TOTAL];
__device__ __half g_wl[W_TOTAL];

// ---------- PTX helpers ----------
__device__ __forceinline__ uint32_t smem_u32(const void* p) {
    uint32_t a;
    asm("{ .reg .u64 t; cvta.to.shared.u64 t, %1; cvt.u32.u64 %0, t; }" : "=r"(a) : "l"(p));
    return a;
}
#define CP_ASYNC16(dst, src) \
    asm volatile("cp.async.cg.shared.global [%0], [%1], 16;" :: "r"(dst), "l"(src))
#define CP_COMMIT() asm volatile("cp.async.commit_group;" ::: "memory")
#define CP_WAIT(n)  asm volatile("cp.async.wait_group %0;" :: "n"(n) : "memory")

__device__ __forceinline__ void ldsm4(uint32_t r[4], uint32_t addr) {
    asm volatile("ldmatrix.sync.aligned.m8n8.x4.shared.b16 {%0,%1,%2,%3}, [%4];"
                 : "=r"(r[0]), "=r"(r[1]), "=r"(r[2]), "=r"(r[3]) : "r"(addr));
}
__device__ __forceinline__ void mma16816(float c[4], const uint32_t a[4], const uint32_t* b) {
    asm volatile(
        "mma.sync.aligned.m16n8k16.row.col.f32.f16.f16.f32 "
        "{%0,%1,%2,%3}, {%4,%5,%6,%7}, {%8,%9}, {%0,%1,%2,%3};"
        : "+f"(c[0]), "+f"(c[1]), "+f"(c[2]), "+f"(c[3])
        : "r"(a[0]), "r"(a[1]), "r"(a[2]), "r"(a[3]), "r"(b[0]), "r"(b[1]));
}

// ---------- activation ----------
__device__ __forceinline__ float act_clip(float h, int f, float mx) {
    float o;
    if (f == 0) {
        o = fmaxf(h, 0.0f);
    } else if (f == 1) {
        o = 1.0f / (1.0f + expf(-h));
    } else if (f == 2) {
        o = tanhf(h);
    } else if (f == 3) {
        o = (h > 0.0f) ? h : 0.1f * h;
    } else {
        const float lam = 1.0507009873554805f;
        const float alp = 1.6732632423543772f;
        o = (h > 0.0f) ? lam * h : lam * alp * expm1f(h);
    }
    return fminf(o, mx);
}

__device__ __forceinline__ uint32_t pack_h2(float x0, float x1) {
    __half2 h = __floats2half2_rn(x0, x1);
    return *(uint32_t*)&h;
}

// ---------- split fp32 -> hi/lo fp16 ----------
__global__ __launch_bounds__(256)
void split_kernel(const float* __restrict__ src, __half* __restrict__ hi,
                  __half* __restrict__ lo, int n)
{
    int i = (blockIdx.x * 256 + threadIdx.x) * 4;
    if (i >= n) return;
    float4 v = *(const float4*)(src + i);
    float x[4] = {v.x, v.y, v.z, v.w};
    float h[4], r[4];
#pragma unroll
    for (int k = 0; k < 4; k++) {
        h[k] = __half2float(__float2half_rn(x[k]));
        r[k] = x[k] - h[k];
    }
    *(uint2*)(hi + i) = make_uint2(pack_h2(h[0], h[1]), pack_h2(h[2], h[3]));
    *(uint2*)(lo + i) = make_uint2(pack_h2(r[0], r[1]), pack_h2(r[2], r[3]));
}

// ============================================================
// C[128,128] tile of act(A @ W^T + b). K = 512.
// 8 warps: 2(M) x 4(N); warp tile 64x32; K-chunks of 32.
// 3-stage cp.async ring (32 KB/stage), prefetch issued after the
// barrier (safe: barrier proves chunk c-1 fully consumed).
// 2 CTAs/SM via __launch_bounds__(256, 2).
// ============================================================
template<bool OUT_FP32>
__global__ __launch_bounds__(256, 2)
void bnn_gemm_kernel(const __half* __restrict__ Ahi,
                     const __half* __restrict__ Alo,
                     const __half* __restrict__ Whi,
                     const __half* __restrict__ Wlo,
                     const float* __restrict__ bias,
                     const int* __restrict__ fid,
                     const float* __restrict__ mcap,
                     float* __restrict__ OutF,
                     __half* __restrict__ Ohi,
                     __half* __restrict__ Olo,
                     int N_total)
{
    extern __shared__ char smem[];
    constexpr int K = 512;
    constexpr int NCHUNK = K / 32;        // 16
    constexpr int TT = 2;                 // 16-col t-tiles per warp
    constexpr int NI = 4;                 // n8 sub-tiles per warp

    // stage: 512 rows x 64B = 32 KB. [Ah 0-127 | Al 128-255 | Bh 256-383 | Bl 384-511]
    constexpr int STAGE  = 512 * 64;
    constexpr int AL_OFF = 128 * 64;
    constexpr int BH_OFF = 256 * 64;
    constexpr int BL_OFF = 384 * 64;

    const int tid  = threadIdx.x;
    const int lane = tid & 31;
    const int wid  = tid >> 5;
    const int mBase = blockIdx.y * 128;
    const int nBase = blockIdx.x * 128;
    const uint32_t sb = smem_u32(smem);

    const int mw = (wid & 1) * 64;        // warp M offset
    const int nw = (wid >> 1) * 32;       // warp N offset

    // ldmatrix lane roles
    const int lA_r = (lane & 7) + ((lane >> 3) & 1) * 8;
    const int lA_c = (lane >> 4) & 1;
    const int lB_r = (lane & 7) + ((lane >> 4) & 1) * 8;
    const int lB_c = (lane >> 3) & 1;

    float acc[4][NI][4];
#pragma unroll
    for (int i = 0; i < 4; i++)
#pragma unroll
        for (int j = 0; j < NI; j++)
#pragma unroll
            for (int v = 0; v < 4; v++) acc[i][j][v] = 0.0f;

    // ---- prefetch state: 4 running plane pointers + constant smem offsets ----
    // thread covers rows rg0 and rg0+64 of each 128-row plane (j even/odd).
    const int rg0 = tid >> 2;             // 0..63
    const int q   = tid & 3;              // 16B chunk in 64B row
    const uint32_t baseOff = (uint32_t)rg0 * 64 + (uint32_t)((q * 16) ^ ((rg0 & 6) << 3));

    const __half* P[4];
    P[0] = Ahi + (size_t)(mBase + rg0) * K + q * 8;
    P[1] = Alo + (size_t)(mBase + rg0) * K + q * 8;
    P[2] = Whi + (size_t)(nBase + rg0) * K + q * 8;
    P[3] = Wlo + (size_t)(nBase + rg0) * K + q * 8;
    const size_t row64 = (size_t)64 * K;  // +64 rows

    auto prefetch = [&](int s) {
        const uint32_t dstb = sb + s * STAGE + baseOff;
#pragma unroll
        for (int j = 0; j < 8; j++) {
            const int p = j >> 1;
            const __half* src = P[p] + (j & 1) * row64;
            CP_ASYNC16(dstb + j * 4096, src);
        }
#pragma unroll
        for (int p = 0; p < 4; p++) P[p] += 32;   // advance k by 32 cols
        CP_COMMIT();
    };

    prefetch(0);
    prefetch(1);

    int sc = 0, sp = 2;                   // compute stage, prefetch stage
#pragma unroll 1
    for (int c = 0; c < NCHUNK; c++) {
        if (c + 1 < NCHUNK) CP_WAIT(1); else CP_WAIT(0);
        __syncthreads();                  // publish chunk c; all warps done with c-1
        if (c + 2 < NCHUNK) {
            prefetch(sp);
            sp = (sp == 2) ? 0 : sp + 1;
        }

        const uint32_t stg = sb + sc * STAGE;
        sc = (sc == 2) ? 0 : sc + 1;
        const uint32_t aH = stg;
        const uint32_t aL = stg + AL_OFF;
        const uint32_t bH = stg + BH_OFF;
        const uint32_t bL = stg + BL_OFF;

#pragma unroll
        for (int ks = 0; ks < 2; ks++) {
            uint32_t ah[4][4], al[4][4];
            const int cA = ks * 2 + lA_c;
#pragma unroll
            for (int mi = 0; mi < 4; mi++) {
                const int r = mw + mi * 16 + lA_r;
                const uint32_t off = r * 64 + ((cA * 16) ^ ((r & 6) << 3));
                ldsm4(ah[mi], aH + off);
                ldsm4(al[mi], aL + off);
            }
            const int cB = ks * 2 + lB_c;
#pragma unroll
            for (int t = 0; t < TT; t++) {
                const int r = nw + t * 16 + lB_r;
                const uint32_t off = r * 64 + ((cB * 16) ^ ((r & 6) << 3));
                uint32_t bh[4], bl[4];
                ldsm4(bh, bH + off);
                ldsm4(bl, bL + off);
                // mi-inner ordering: 8-MMA reuse distance per accumulator.
#pragma unroll
                for (int mi = 0; mi < 4; mi++) mma16816(acc[mi][2 * t],     ah[mi], bh);
#pragma unroll
                for (int mi = 0; mi < 4; mi++) mma16816(acc[mi][2 * t + 1], ah[mi], bh + 2);
#pragma unroll
                for (int mi = 0; mi < 4; mi++) mma16816(acc[mi][2 * t],     ah[mi], bl);
#pragma unroll
                for (int mi = 0; mi < 4; mi++) mma16816(acc[mi][2 * t + 1], ah[mi], bl + 2);
#pragma unroll
                for (int mi = 0; mi < 4; mi++) mma16816(acc[mi][2 * t],     al[mi], bh);
#pragma unroll
                for (int mi = 0; mi < 4; mi++) mma16816(acc[mi][2 * t + 1], al[mi], bh + 2);
            }
        }
    }

    // ---------- epilogue ----------
    const int colq = (lane & 3) * 2;
#pragma unroll
    for (int ni = 0; ni < NI; ni++) {
        const int col = nBase + nw + ni * 8 + colq;
        const float2 b2 = *(const float2*)(bias + col);
        const int2   f2 = *(const int2*)(fid + col);
        const float2 m2 = *(const float2*)(mcap + col);
#pragma unroll
        for (int mi = 0; mi < 4; mi++) {
#pragma unroll
            for (int h = 0; h < 2; h++) {
                const int row = mBase + mw + mi * 16 + (lane >> 2) + h * 8;
                const float r0 = act_clip(acc[mi][ni][h * 2 + 0] + b2.x, f2.x, m2.x);
                const float r1 = act_clip(acc[mi][ni][h * 2 + 1] + b2.y, f2.y, m2.y);
                const size_t o = (size_t)row * N_total + col;
                if (OUT_FP32) {
                    *(float2*)(OutF + o) = make_float2(r0, r1);
                } else {
                    const float h0 = __half2float(__float2half_rn(r0));
                    const float h1 = __half2float(__float2half_rn(r1));
                    *(uint32_t*)(Ohi + o) = pack_h2(r0, r1);
                    *(uint32_t*)(Olo + o) = pack_h2(r0 - h0, r1 - h1);
                }
            }
        }
    }
}

// ============================================================
extern "C" void kernel_launch(void* const* d_in, const int* in_sizes, int n_in,
                              void* d_out, int out_size)
{
    const float* input  = (const float*)d_in[0];
    const float* W_in   = (const float*)d_in[1];
    const float* b_in   = (const float*)d_in[2];
    const float* W_h    = (const float*)d_in[3];
    const float* b_h    = (const float*)d_in[4];
    const float* W_out  = (const float*)d_in[5];
    const float* b_out  = (const float*)d_in[6];
    const float* m_in   = (const float*)d_in[7];
    const float* m_h    = (const float*)d_in[8];
    const float* m_out  = (const float*)d_in[9];
    const int*   fid_in  = (const int*)d_in[10];
    const int*   fid_h   = (const int*)d_in[11];
    const int*   fid_out = (const int*)d_in[12];
    float* out = (float*)d_out;

    __half *ah0, *al0, *ah1, *al1, *wh, *wl;
    cudaGetSymbolAddress((void**)&ah0, g_ah0);
    cudaGetSymbolAddress((void**)&al0, g_al0);
    cudaGetSymbolAddress((void**)&ah1, g_ah1);
    cudaGetSymbolAddress((void**)&al1, g_al1);
    cudaGetSymbolAddress((void**)&wh, g_wh);
    cudaGetSymbolAddress((void**)&wl, g_wl);

    constexpr int SMEM = 3 * 512 * 64;   // 98304 (3 stages x 32 KB)
    cudaFuncSetAttribute(bnn_gemm_kernel<false>,
                         cudaFuncAttributeMaxDynamicSharedMemorySize, SMEM);
    cudaFuncSetAttribute(bnn_gemm_kernel<true>,
                         cudaFuncAttributeMaxDynamicSharedMemorySize, SMEM);

    const int B = BATCH, X = XDIM, DOUT = 128;
    const int WIN_OFF = 0, WH_OFF = X * X, WOUT_OFF = 5 * X * X;

    // fp32 -> hi/lo fp16 splits
    split_kernel<<<(B * X) / 1024, 256>>>(input, ah0, al0, B * X);
    split_kernel<<<(X * X) / 1024, 256>>>(W_in, wh + WIN_OFF, wl + WIN_OFF, X * X);
    split_kernel<<<(4 * X * X) / 1024, 256>>>(W_h, wh + WH_OFF, wl + WH_OFF, 4 * X * X);
    split_kernel<<<(DOUT * X) / 1024, 256>>>(W_out, wh + WOUT_OFF, wl + WOUT_OFF, DOUT * X);

    dim3 blk(256);
    dim3 grid512(X / 128, B / 128);    // (4, 512)
    dim3 grid128(1, B / 128);          // (1, 512)

    // layer 1
    bnn_gemm_kernel<false><<<grid512, blk, SMEM>>>(
        ah0, al0, wh + WIN_OFF, wl + WIN_OFF, b_in, fid_in, m_in,
        nullptr, ah1, al1, X);

    // hidden layers
    __half *ch = ah1, *cl = al1, *nh = ah0, *nl = al0;
    for (int i = 0; i < 4; i++) {
        bnn_gemm_kernel<false><<<grid512, blk, SMEM>>>(
            ch, cl, wh + WH_OFF + i * X * X, wl + WH_OFF + i * X * X,
            b_h + i * X, fid_h + i * X, m_h + i * X,
            nullptr, nh, nl, X);
        __half* t;
        t = ch; ch = nh; nh = t;
        t = cl; cl = nl; nl = t;
    }

    // output layer -> fp32
    bnn_gemm_kernel<true><<<grid128, blk, SMEM>>>(
        ch, cl, wh + WOUT_OFF, wl + WOUT_OFF, b_out, fid_out, m_out,
        out, nullptr, nullptr, DOUT);
}